// round 5
// baseline (speedup 1.0000x reference)
#include <cuda_runtime.h>

// LSTM autoencoder: enc (F=32 -> H=64), dec (H=64 -> F=32), B=512, T=1024.
// 128 blocks x 768 threads (6 warps/SMSP), 4 batch rows/block.
// tid = ug*8 + p*4 + q:  ug = unit (0..63 enc, 64..95 dec),
//   p = gate pair (0:(i,f), 1:(g,o)),  q = k-quarter AND elementwise row.
// Thread: 2 gates x 24 k-floats (12 packed f32x2 each, 48 regs) x 4 rows
//   = 96 FFMA2/step, accumulated with row permutation a[l] = row (q^l)
//   so the quad reduction is a pure shfl butterfly (no selects):
//   full(row q) = (a0 + sx(a1,1)) + sx(a2 + sx(a3,1), 2); pair swap via sx(.,4).
// Elementwise computed redundantly by both p-threads (uniform warps),
// stores predicated on p==0. Biases in SMEM. Double-buffered xh state,
// ONE __syncthreads per step. Decoder lags encoder by one step.

#define T_STEPS 1024
#define FDIM    32
#define HDIM    64
#define ROWS    4
#define NBLK    128
#define NTHR    768
#define XHP     104

#define OFF_XHE(b) ((b) * (ROWS * XHP))
#define OFF_XHD(b) (2 * ROWS * XHP + (b) * (ROWS * XHP))
#define OFF_BE     (4 * ROWS * XHP)          // 1664: enc bias [256]
#define OFF_BD     (OFF_BE + 256)            // 1920: dec bias [128]
#define SMEMN      (OFF_BD + 128)            // 2048 floats = 8 KB

typedef unsigned long long ull;
union U64F2 { ull u; float2 f; };

__device__ __forceinline__ ull pk(float lo, float hi) {
    U64F2 u; u.f = make_float2(lo, hi); return u.u;
}
__device__ __forceinline__ ull ffma2(ull a, ull b, ull c) {
    ull d;
    asm("fma.rn.f32x2 %0, %1, %2, %3;" : "=l"(d) : "l"(a), "l"(b), "l"(c));
    return d;
}
__device__ __forceinline__ float hsum2(ull a) {
    U64F2 u; u.u = a; return u.f.x + u.f.y;
}
__device__ __forceinline__ float sigf(float x) {
    return __fdividef(1.0f, 1.0f + __expf(-x));
}
__device__ __forceinline__ float tanh_fast(float x) {
    float e = __expf(2.0f * x);
    return 1.0f - __fdividef(2.0f, e + 1.0f);
}

__global__ void __launch_bounds__(NTHR, 1) lstm_ae_kernel(
    const float* __restrict__ x,
    const float* __restrict__ ew_ih, const float* __restrict__ ew_hh,
    const float* __restrict__ eb_ih, const float* __restrict__ eb_hh,
    const float* __restrict__ dw_ih, const float* __restrict__ dw_hh,
    const float* __restrict__ db_ih, const float* __restrict__ db_hh,
    float* __restrict__ out)
{
    __shared__ __align__(16) float sm[SMEMN];
    const int tid = threadIdx.x;
    const int b0  = blockIdx.x * ROWS;

    const int ug   = tid >> 3;            // unit 0..95
    const bool dec = (ug >= 64);
    const int u    = dec ? (ug - 64) : ug;
    const int p    = (tid >> 2) & 1;      // gate pair
    const int q    = tid & 3;             // k-quarter & ew row
    const int kb   = 24 * q;

    // ---- weights -> registers: 2 gates x 24 floats ----
    ull wA[12], wB[12];
    {
        const int U  = dec ? FDIM : HDIM;
        const int gA = u + (p ? 2 * U : 0);
        const int gB = gA + U;
        const int KI = dec ? HDIM : FDIM;
        const int KH = dec ? FDIM : HDIM;
        const float* wih = dec ? dw_ih : ew_ih;
        const float* whh = dec ? dw_hh : ew_hh;
        #pragma unroll
        for (int j = 0; j < 12; ++j) {
            const int k0 = kb + 2 * j, k1 = k0 + 1;
            float a0  = (k0 < KI) ? wih[gA * KI + k0] : whh[gA * KH + (k0 - KI)];
            float a1  = (k1 < KI) ? wih[gA * KI + k1] : whh[gA * KH + (k1 - KI)];
            float b0v = (k0 < KI) ? wih[gB * KI + k0] : whh[gB * KH + (k0 - KI)];
            float b1v = (k1 < KI) ? wih[gB * KI + k1] : whh[gB * KH + (k1 - KI)];
            wA[j] = pk(a0, a1);
            wB[j] = pk(b0v, b1v);
        }
    }

    // ---- biases + state init ----
    for (int i = tid; i < SMEMN; i += NTHR) sm[i] = 0.0f;
    __syncthreads();
    if (tid < 256) sm[OFF_BE + tid] = eb_ih[tid] + eb_hh[tid];
    else if (tid < 384) sm[OFF_BD + tid - 256] = db_ih[tid - 256] + db_hh[tid - 256];
    // x(0) into XHE(0); prefetch x(1). dec p==1 threads cover 4 rows x 32 feats.
    float x_pref = 0.0f;
    if (dec && p == 1) {
        sm[OFF_XHE(0) + q * XHP + u] =
            x[((size_t)(b0 + q) * T_STEPS + 0) * FDIM + u];
        x_pref = x[((size_t)(b0 + q) * T_STEPS + 1) * FDIM + u];
    }
    __syncthreads();

    // bias pointers for this unit
    const float* bias = sm + (dec ? OFF_BD : OFF_BE);
    const int U2 = dec ? FDIM : HDIM;

    // row byte-offsets in permuted order (q^l)
    int ro0 = (q)     * XHP;
    int ro1 = (q ^ 1) * XHP;
    int ro2 = (q ^ 2) * XHP;
    int ro3 = (q ^ 3) * XHP;

    float c_st = 0.0f;

    for (int it = 0; it <= T_STEPS; ++it) {
        const int rb = it & 1, wb = rb ^ 1;
        const float* xh = sm + (dec ? OFF_XHD(rb) : OFF_XHE(rb)) + kb;

        // ===== FMA: 2 gates x 4 rows (row-permuted accumulators) =====
        float aA0, aA1, aA2, aA3, aB0, aB1, aB2, aB3;
        {
            const ulonglong2* hp;
            ull cA, cB;
            #define DO_ROW(RO, OUTA, OUTB)                                   \
                hp = reinterpret_cast<const ulonglong2*>(xh + (RO));         \
                cA = 0ull; cB = 0ull;                                        \
                _Pragma("unroll")                                            \
                for (int c = 0; c < 6; ++c) {                                \
                    ulonglong2 v = hp[c];                                    \
                    cA = ffma2(wA[2 * c],     v.x, cA);                      \
                    cA = ffma2(wA[2 * c + 1], v.y, cA);                      \
                    cB = ffma2(wB[2 * c],     v.x, cB);                      \
                    cB = ffma2(wB[2 * c + 1], v.y, cB);                      \
                }                                                            \
                OUTA = hsum2(cA); OUTB = hsum2(cB);
            DO_ROW(ro0, aA0, aB0)
            DO_ROW(ro1, aA1, aB1)
            DO_ROW(ro2, aA2, aB2)
            DO_ROW(ro3, aA3, aB3)
            #undef DO_ROW
        }

        // ===== butterfly reduction over k-quarters, then gate-pair swap =====
        float tA0 = aA0 + __shfl_xor_sync(0xFFFFFFFFu, aA1, 1);
        float tA1 = aA2 + __shfl_xor_sync(0xFFFFFFFFu, aA3, 1);
        float fA  = tA0 + __shfl_xor_sync(0xFFFFFFFFu, tA1, 2);
        float tB0 = aB0 + __shfl_xor_sync(0xFFFFFFFFu, aB1, 1);
        float tB1 = aB2 + __shfl_xor_sync(0xFFFFFFFFu, aB3, 1);
        float fB  = tB0 + __shfl_xor_sync(0xFFFFFFFFu, tB1, 2);
        float pA  = __shfl_xor_sync(0xFFFFFFFFu, fA, 4);
        float pB  = __shfl_xor_sync(0xFFFFFFFFu, fB, 4);

        float gi = (p ? pA : fA) + bias[u];
        float gf = (p ? pB : fB) + bias[u + U2];
        float gg = (p ? fA : pA) + bias[u + 2 * U2];
        float go = (p ? fB : pB) + bias[u + 3 * U2];

        // ===== elementwise (redundant across p; uniform per warp) =====
        const bool live = dec ? (it > 0) : (it < T_STEPS);
        if (live) {
            float iv = sigf(gi), fv = sigf(gf);
            float gv = tanh_fast(gg), ov = sigf(go);
            c_st = fv * c_st + iv * gv;
            float hv = ov * tanh_fast(c_st);
            if (p == 0) {
                if (!dec) {
                    sm[OFF_XHE(wb) + q * XHP + FDIM + u] = hv;  // enc recurrence
                    sm[OFF_XHD(wb) + q * XHP + u]        = hv;  // dec input
                } else {
                    sm[OFF_XHD(wb) + q * XHP + HDIM + u] = hv;  // dec recurrence
                    out[((size_t)(b0 + q) * T_STEPS + (it - 1)) * FDIM + u] = hv;
                }
            }
        }
        if (dec && p == 1) {   // x pipeline
            if (it + 1 < T_STEPS)
                sm[OFF_XHE(wb) + q * XHP + u] = x_pref;
            if (it + 2 < T_STEPS)
                x_pref = x[((size_t)(b0 + q) * T_STEPS + (it + 2)) * FDIM + u];
        }
        __syncthreads();
    }
}

extern "C" void kernel_launch(void* const* d_in, const int* in_sizes, int n_in,
                              void* d_out, int out_size)
{
    (void)in_sizes; (void)n_in; (void)out_size;
    lstm_ae_kernel<<<NBLK, NTHR>>>(
        (const float*)d_in[0],
        (const float*)d_in[1], (const float*)d_in[2],
        (const float*)d_in[3], (const float*)d_in[4],
        (const float*)d_in[5], (const float*)d_in[6],
        (const float*)d_in[7], (const float*)d_in[8],
        (float*)d_out);
}

// round 6
// speedup vs baseline: 1.9576x; 1.9576x over previous
#include <cuda_runtime.h>

// LSTM autoencoder: enc (F=32 -> H=64), dec (H=64 -> F=32), B=512, T=1024.
// 128 blocks x 384 threads (3 warps/SMSP), 4 batch rows/block.
// tid = ug*4 + q:  ug = unit (0..63 enc, 64..95 dec), q = k-quarter AND ew row.
// Thread holds ALL 4 gates (i,f,g,o) of its unit over k-quarter [24q,24q+24):
//   4 x 12 packed f32x2 = 48 weight regs, 192 FFMA2/step over 4 rows.
// Row-permuted accumulators a[l] = partial(row q^l, quarter q) make the
// k-quarter reduction a pure shfl butterfly (3 shfl per gate, 12 total);
// afterwards each thread owns complete i,f,g,o for (unit, row q) -> ew is
// non-redundant with zero selects. hv LDS.128 halved vs prior round (24/step).
// Double-buffered xh state, ONE __syncthreads per step, decoder lags 1 step.

#define T_STEPS 1024
#define FDIM    32
#define HDIM    64
#define ROWS    4
#define NBLK    128
#define NTHR    384
#define XHP     104

#define OFF_XHE(b) ((b) * (ROWS * XHP))
#define OFF_XHD(b) (2 * ROWS * XHP + (b) * (ROWS * XHP))
#define SMEMN      (4 * ROWS * XHP)

typedef unsigned long long ull;
union U64F2 { ull u; float2 f; };

__device__ __forceinline__ ull pk(float lo, float hi) {
    U64F2 u; u.f = make_float2(lo, hi); return u.u;
}
__device__ __forceinline__ ull ffma2(ull a, ull b, ull c) {
    ull d;
    asm("fma.rn.f32x2 %0, %1, %2, %3;" : "=l"(d) : "l"(a), "l"(b), "l"(c));
    return d;
}
__device__ __forceinline__ float hsum2(ull a) {
    U64F2 u; u.u = a; return u.f.x + u.f.y;
}
__device__ __forceinline__ float sigf(float x) {
    return __fdividef(1.0f, 1.0f + __expf(-x));
}
__device__ __forceinline__ float tanh_fast(float x) {
    float e = __expf(2.0f * x);
    return 1.0f - __fdividef(2.0f, e + 1.0f);
}

__global__ void __launch_bounds__(NTHR, 1) lstm_ae_kernel(
    const float* __restrict__ x,
    const float* __restrict__ ew_ih, const float* __restrict__ ew_hh,
    const float* __restrict__ eb_ih, const float* __restrict__ eb_hh,
    const float* __restrict__ dw_ih, const float* __restrict__ dw_hh,
    const float* __restrict__ db_ih, const float* __restrict__ db_hh,
    float* __restrict__ out)
{
    __shared__ __align__(16) float sm[SMEMN];
    const int tid = threadIdx.x;
    const int b0  = blockIdx.x * ROWS;

    const int ug   = tid >> 2;            // unit 0..95 (warp-aligned enc/dec split)
    const bool dec = (ug >= 64);
    const int u    = dec ? (ug - 64) : ug;
    const int q    = tid & 3;             // k-quarter AND elementwise row
    const int kb   = 24 * q;

    // ---- weights -> registers: 4 gates x 24 k-floats (12 packed each) ----
    ull wI[12], wF[12], wG[12], wO[12];
    {
        const int U  = dec ? FDIM : HDIM;
        const int KI = dec ? HDIM : FDIM;
        const int KH = dec ? FDIM : HDIM;
        const float* wih = dec ? dw_ih : ew_ih;
        const float* whh = dec ? dw_hh : ew_hh;
        #pragma unroll
        for (int j = 0; j < 12; ++j) {
            const int k0 = kb + 2 * j, k1 = k0 + 1;
            #define WLD(ARR, GOFF)                                              \
            {                                                                   \
                const int g = u + (GOFF) * U;                                   \
                float lo = (k0 < KI) ? wih[g * KI + k0] : whh[g * KH + (k0 - KI)]; \
                float hi = (k1 < KI) ? wih[g * KI + k1] : whh[g * KH + (k1 - KI)]; \
                ARR[j] = pk(lo, hi);                                            \
            }
            WLD(wI, 0) WLD(wF, 1) WLD(wG, 2) WLD(wO, 3)
            #undef WLD
        }
    }

    // ---- biases for this unit ----
    const int U2 = dec ? FDIM : HDIM;
    const float* bih = dec ? db_ih : eb_ih;
    const float* bhh = dec ? db_hh : eb_hh;
    const float bi = bih[u]          + bhh[u];
    const float bf = bih[u + U2]     + bhh[u + U2];
    const float bg = bih[u + 2 * U2] + bhh[u + 2 * U2];
    const float bo = bih[u + 3 * U2] + bhh[u + 3 * U2];

    // ---- init state; x(0) in, prefetch x(1) (dec threads cover 4x32 slots) ----
    for (int i = tid; i < SMEMN; i += NTHR) sm[i] = 0.0f;
    __syncthreads();
    float x_pref = 0.0f;
    if (dec) {
        sm[OFF_XHE(0) + q * XHP + u] =
            x[((size_t)(b0 + q) * T_STEPS + 0) * FDIM + u];
        x_pref = x[((size_t)(b0 + q) * T_STEPS + 1) * FDIM + u];
    }
    __syncthreads();

    // row offsets in permuted order (q^l)
    const int ro0 = (q)     * XHP;
    const int ro1 = (q ^ 1) * XHP;
    const int ro2 = (q ^ 2) * XHP;
    const int ro3 = (q ^ 3) * XHP;

    float c_st = 0.0f;

    for (int it = 0; it <= T_STEPS; ++it) {
        const int rb = it & 1, wb = rb ^ 1;
        const bool live = dec ? (it > 0) : (it < T_STEPS);
        const float* xh = sm + (dec ? OFF_XHD(rb) : OFF_XHE(rb)) + kb;

        // ===== FMA: 4 gates x 4 rows (row-permuted accumulators) =====
        float aI[4], aF[4], aG[4], aO[4];
        {
            #define DO_ROW(L, RO)                                            \
            {                                                                \
                const ulonglong2* hp =                                       \
                    reinterpret_cast<const ulonglong2*>(xh + (RO));          \
                ull cI = 0ull, cF = 0ull, cG = 0ull, cO = 0ull;              \
                _Pragma("unroll")                                            \
                for (int c = 0; c < 6; ++c) {                                \
                    ulonglong2 v = hp[c];                                    \
                    cI = ffma2(wI[2 * c], v.x, cI);                          \
                    cF = ffma2(wF[2 * c], v.x, cF);                          \
                    cG = ffma2(wG[2 * c], v.x, cG);                          \
                    cO = ffma2(wO[2 * c], v.x, cO);                          \
                    cI = ffma2(wI[2 * c + 1], v.y, cI);                      \
                    cF = ffma2(wF[2 * c + 1], v.y, cF);                      \
                    cG = ffma2(wG[2 * c + 1], v.y, cG);                      \
                    cO = ffma2(wO[2 * c + 1], v.y, cO);                      \
                }                                                            \
                aI[L] = hsum2(cI); aF[L] = hsum2(cF);                        \
                aG[L] = hsum2(cG); aO[L] = hsum2(cO);                        \
            }
            DO_ROW(0, ro0)
            DO_ROW(1, ro1)
            DO_ROW(2, ro2)
            DO_ROW(3, ro3)
            #undef DO_ROW
        }

        // ===== butterfly reduction over k-quarters (3 shfl/gate) =====
        // lane q, a[l] = partial(row q^l, quarter q)  ->  full(row q)
        #define REDUCE(A, OUTV)                                              \
        {                                                                    \
            float t0 = A[0] + __shfl_xor_sync(0xFFFFFFFFu, A[1], 1);         \
            float t1 = A[2] + __shfl_xor_sync(0xFFFFFFFFu, A[3], 1);         \
            OUTV = t0 + __shfl_xor_sync(0xFFFFFFFFu, t1, 2);                 \
        }
        float gi, gf, gg, go;
        REDUCE(aI, gi) REDUCE(aF, gf) REDUCE(aG, gg) REDUCE(aO, go)
        #undef REDUCE
        gi += bi; gf += bf; gg += bg; go += bo;

        // ===== elementwise (non-redundant: this thread owns (unit, row q)) =====
        if (live) {
            float iv = sigf(gi), fv = sigf(gf);
            float gv = tanh_fast(gg), ov = sigf(go);
            c_st = fv * c_st + iv * gv;
            float hv = ov * tanh_fast(c_st);
            if (!dec) {
                sm[OFF_XHE(wb) + q * XHP + FDIM + u] = hv;  // enc recurrence
                sm[OFF_XHD(wb) + q * XHP + u]        = hv;  // dec input
            } else {
                sm[OFF_XHD(wb) + q * XHP + HDIM + u] = hv;  // dec recurrence
                out[((size_t)(b0 + q) * T_STEPS + (it - 1)) * FDIM + u] = hv;
            }
        }
        if (dec) {   // x pipeline
            if (it + 1 < T_STEPS)
                sm[OFF_XHE(wb) + q * XHP + u] = x_pref;
            if (it + 2 < T_STEPS)
                x_pref = x[((size_t)(b0 + q) * T_STEPS + (it + 2)) * FDIM + u];
        }
        __syncthreads();
    }
}

extern "C" void kernel_launch(void* const* d_in, const int* in_sizes, int n_in,
                              void* d_out, int out_size)
{
    (void)in_sizes; (void)n_in; (void)out_size;
    lstm_ae_kernel<<<NBLK, NTHR>>>(
        (const float*)d_in[0],
        (const float*)d_in[1], (const float*)d_in[2],
        (const float*)d_in[3], (const float*)d_in[4],
        (const float*)d_in[5], (const float*)d_in[6],
        (const float*)d_in[7], (const float*)d_in[8],
        (float*)d_out);
}

// round 7
// speedup vs baseline: 3.5508x; 1.8138x over previous
#include <cuda_runtime.h>

// LSTM autoencoder: enc (F=32 -> H=64), dec (H=64 -> F=32), B=512, T=1024.
// 128 blocks x 384 threads (3 warps/SMSP), 4 batch rows/block.
// tid = ug*4 + q:  ug = unit (0..63 enc, 64..95 dec), q = k-quarter AND ew row.
// Thread holds ALL 4 gates (i,f,g,o) of its unit over k-quarter [24q,24q+24):
//   4 x 12 packed f32x2 = 48 weight regs, 192 FFMA2/step over 4 rows.
// Row-permuted accumulators a[l] = partial(row q^l, quarter q) make the
// k-quarter reduction a pure shfl butterfly (3 shfl per gate, 12 total).
// XHP = 100 (== 4 mod 32 banks): hv load bank base (q^l)*4 + 24q is distinct
// across q for every l -> CONFLICT-FREE LDS.128 (this was the R6 bug: XHP=104
// made (104+24)q == 0 mod 32, a 4-way conflict on every l=0 load).
// Double-buffered xh state, ONE __syncthreads per step, decoder lags 1 step.

#define T_STEPS 1024
#define FDIM    32
#define HDIM    64
#define ROWS    4
#define NBLK    128
#define NTHR    384
#define XHP     100

#define OFF_XHE(b) ((b) * (ROWS * XHP))
#define OFF_XHD(b) (2 * ROWS * XHP + (b) * (ROWS * XHP))
#define SMEMN      (4 * ROWS * XHP)

typedef unsigned long long ull;
union U64F2 { ull u; float2 f; };

__device__ __forceinline__ ull pk(float lo, float hi) {
    U64F2 u; u.f = make_float2(lo, hi); return u.u;
}
__device__ __forceinline__ ull ffma2(ull a, ull b, ull c) {
    ull d;
    asm("fma.rn.f32x2 %0, %1, %2, %3;" : "=l"(d) : "l"(a), "l"(b), "l"(c));
    return d;
}
__device__ __forceinline__ float hsum2(ull a) {
    U64F2 u; u.u = a; return u.f.x + u.f.y;
}
__device__ __forceinline__ float sigf(float x) {
    return __fdividef(1.0f, 1.0f + __expf(-x));
}
__device__ __forceinline__ float tanh_fast(float x) {
    float e = __expf(2.0f * x);
    return 1.0f - __fdividef(2.0f, e + 1.0f);
}

__global__ void __launch_bounds__(NTHR, 1) lstm_ae_kernel(
    const float* __restrict__ x,
    const float* __restrict__ ew_ih, const float* __restrict__ ew_hh,
    const float* __restrict__ eb_ih, const float* __restrict__ eb_hh,
    const float* __restrict__ dw_ih, const float* __restrict__ dw_hh,
    const float* __restrict__ db_ih, const float* __restrict__ db_hh,
    float* __restrict__ out)
{
    __shared__ __align__(16) float sm[SMEMN];
    const int tid = threadIdx.x;
    const int b0  = blockIdx.x * ROWS;

    const int ug   = tid >> 2;            // unit 0..95 (warp-aligned enc/dec split)
    const bool dec = (ug >= 64);
    const int u    = dec ? (ug - 64) : ug;
    const int q    = tid & 3;             // k-quarter AND elementwise row
    const int kb   = 24 * q;

    // ---- weights -> registers: 4 gates x 24 k-floats (12 packed each) ----
    ull wI[12], wF[12], wG[12], wO[12];
    {
        const int U  = dec ? FDIM : HDIM;
        const int KI = dec ? HDIM : FDIM;
        const int KH = dec ? FDIM : HDIM;
        const float* wih = dec ? dw_ih : ew_ih;
        const float* whh = dec ? dw_hh : ew_hh;
        #pragma unroll
        for (int j = 0; j < 12; ++j) {
            const int k0 = kb + 2 * j, k1 = k0 + 1;
            #define WLD(ARR, GOFF)                                              \
            {                                                                   \
                const int g = u + (GOFF) * U;                                   \
                float lo = (k0 < KI) ? wih[g * KI + k0] : whh[g * KH + (k0 - KI)]; \
                float hi = (k1 < KI) ? wih[g * KI + k1] : whh[g * KH + (k1 - KI)]; \
                ARR[j] = pk(lo, hi);                                            \
            }
            WLD(wI, 0) WLD(wF, 1) WLD(wG, 2) WLD(wO, 3)
            #undef WLD
        }
    }

    // ---- biases for this unit ----
    const int U2 = dec ? FDIM : HDIM;
    const float* bih = dec ? db_ih : eb_ih;
    const float* bhh = dec ? db_hh : eb_hh;
    const float bi = bih[u]          + bhh[u];
    const float bf = bih[u + U2]     + bhh[u + U2];
    const float bg = bih[u + 2 * U2] + bhh[u + 2 * U2];
    const float bo = bih[u + 3 * U2] + bhh[u + 3 * U2];

    // ---- init state; x(0) in, prefetch x(1) (dec threads cover 4x32 slots) ----
    for (int i = tid; i < SMEMN; i += NTHR) sm[i] = 0.0f;
    __syncthreads();
    float x_pref = 0.0f;
    if (dec) {
        sm[OFF_XHE(0) + q * XHP + u] =
            x[((size_t)(b0 + q) * T_STEPS + 0) * FDIM + u];
        x_pref = x[((size_t)(b0 + q) * T_STEPS + 1) * FDIM + u];
    }
    __syncthreads();

    // row offsets in permuted order (q^l)
    const int ro0 = (q)     * XHP;
    const int ro1 = (q ^ 1) * XHP;
    const int ro2 = (q ^ 2) * XHP;
    const int ro3 = (q ^ 3) * XHP;

    float c_st = 0.0f;

    for (int it = 0; it <= T_STEPS; ++it) {
        const int rb = it & 1, wb = rb ^ 1;
        const bool live = dec ? (it > 0) : (it < T_STEPS);
        const float* xh = sm + (dec ? OFF_XHD(rb) : OFF_XHE(rb)) + kb;

        // ===== FMA: 4 gates x 4 rows (row-permuted accumulators) =====
        float aI[4], aF[4], aG[4], aO[4];
        {
            #define DO_ROW(L, RO)                                            \
            {                                                                \
                const ulonglong2* hp =                                       \
                    reinterpret_cast<const ulonglong2*>(xh + (RO));          \
                ull cI = 0ull, cF = 0ull, cG = 0ull, cO = 0ull;              \
                _Pragma("unroll")                                            \
                for (int c = 0; c < 6; ++c) {                                \
                    ulonglong2 v = hp[c];                                    \
                    cI = ffma2(wI[2 * c], v.x, cI);                          \
                    cF = ffma2(wF[2 * c], v.x, cF);                          \
                    cG = ffma2(wG[2 * c], v.x, cG);                          \
                    cO = ffma2(wO[2 * c], v.x, cO);                          \
                    cI = ffma2(wI[2 * c + 1], v.y, cI);                      \
                    cF = ffma2(wF[2 * c + 1], v.y, cF);                      \
                    cG = ffma2(wG[2 * c + 1], v.y, cG);                      \
                    cO = ffma2(wO[2 * c + 1], v.y, cO);                      \
                }                                                            \
                aI[L] = hsum2(cI); aF[L] = hsum2(cF);                        \
                aG[L] = hsum2(cG); aO[L] = hsum2(cO);                        \
            }
            DO_ROW(0, ro0)
            DO_ROW(1, ro1)
            DO_ROW(2, ro2)
            DO_ROW(3, ro3)
            #undef DO_ROW
        }

        // ===== butterfly reduction over k-quarters (3 shfl/gate) =====
        // lane q, a[l] = partial(row q^l, quarter q)  ->  full(row q)
        #define REDUCE(A, OUTV)                                              \
        {                                                                    \
            float t0 = A[0] + __shfl_xor_sync(0xFFFFFFFFu, A[1], 1);         \
            float t1 = A[2] + __shfl_xor_sync(0xFFFFFFFFu, A[3], 1);         \
            OUTV = t0 + __shfl_xor_sync(0xFFFFFFFFu, t1, 2);                 \
        }
        float gi, gf, gg, go;
        REDUCE(aI, gi) REDUCE(aF, gf) REDUCE(aG, gg) REDUCE(aO, go)
        #undef REDUCE
        gi += bi; gf += bf; gg += bg; go += bo;

        // ===== elementwise (non-redundant: this thread owns (unit, row q)) =====
        if (live) {
            float iv = sigf(gi), fv = sigf(gf);
            float gv = tanh_fast(gg), ov = sigf(go);
            c_st = fv * c_st + iv * gv;
            float hv = ov * tanh_fast(c_st);
            if (!dec) {
                sm[OFF_XHE(wb) + q * XHP + FDIM + u] = hv;  // enc recurrence
                sm[OFF_XHD(wb) + q * XHP + u]        = hv;  // dec input
            } else {
                sm[OFF_XHD(wb) + q * XHP + HDIM + u] = hv;  // dec recurrence
                out[((size_t)(b0 + q) * T_STEPS + (it - 1)) * FDIM + u] = hv;
            }
        }
        if (dec) {   // x pipeline
            if (it + 1 < T_STEPS)
                sm[OFF_XHE(wb) + q * XHP + u] = x_pref;
            if (it + 2 < T_STEPS)
                x_pref = x[((size_t)(b0 + q) * T_STEPS + (it + 2)) * FDIM + u];
        }
        __syncthreads();
    }
}

extern "C" void kernel_launch(void* const* d_in, const int* in_sizes, int n_in,
                              void* d_out, int out_size)
{
    (void)in_sizes; (void)n_in; (void)out_size;
    lstm_ae_kernel<<<NBLK, NTHR>>>(
        (const float*)d_in[0],
        (const float*)d_in[1], (const float*)d_in[2],
        (const float*)d_in[3], (const float*)d_in[4],
        (const float*)d_in[5], (const float*)d_in[6],
        (const float*)d_in[7], (const float*)d_in[8],
        (float*)d_out);
}